// round 1
// baseline (speedup 1.0000x reference)
#include <cuda_runtime.h>
#include <math.h>

// ---------------------------------------------------------------------------
// Problem constants
//   x        [2048, 49, 512]   fp32
//   mask     [64, 49, 49]      fp32
//   bias_tab [169, 16]         fp32
//   w_qkv    [512, 1536]       fp32
//   w_proj   [512, 512]        fp32
//   out      [2048, 49, 512]   fp32
// ---------------------------------------------------------------------------

#define B_TOT   2048
#define L_TOK   49
#define C_DIM   512
#define H_HEADS 16
#define HD_DIM  32
#define ROWS    (B_TOT * L_TOK)        // 100352 = 784 * 128

// Scratch (device globals; allocation-free per harness rules)
static __device__ float g_qkv[(size_t)ROWS * 3 * C_DIM];  // 616 MB
static __device__ float g_att[(size_t)ROWS * C_DIM];      // 205 MB

// ---------------------------------------------------------------------------
// SGEMM: C[M,N] = A[M,K] * B[K,N], 128x128 tile, BK=8, 256 thr, 8x8 microtile.
// M % 128 == 0, N % 128 == 0, K % 8 == 0 (all true here).
// ---------------------------------------------------------------------------
__global__ __launch_bounds__(256, 2)
void sgemm128(const float* __restrict__ A, const float* __restrict__ B,
              float* __restrict__ C, int M, int N, int K) {
    __shared__ float As[8][128];
    __shared__ float Bs[8][128];

    const int tid = threadIdx.x;
    const int m0  = blockIdx.y * 128;
    const int n0  = blockIdx.x * 128;
    const int ty  = tid >> 4;
    const int tx  = tid & 15;
    const int row0 = ty * 8;
    const int col0 = tx * 8;

    const int aRow = tid >> 1;
    const int aCol = (tid & 1) * 4;
    const int bRow = tid >> 5;
    const int bCol = (tid & 31) * 4;

    float acc[8][8];
    #pragma unroll
    for (int i = 0; i < 8; ++i)
        #pragma unroll
        for (int j = 0; j < 8; ++j) acc[i][j] = 0.f;

    for (int k0 = 0; k0 < K; k0 += 8) {
        float4 av = *(const float4*)&A[(size_t)(m0 + aRow) * K + k0 + aCol];
        float4 bv = *(const float4*)&B[(size_t)(k0 + bRow) * N + n0 + bCol];
        As[aCol + 0][aRow] = av.x;
        As[aCol + 1][aRow] = av.y;
        As[aCol + 2][aRow] = av.z;
        As[aCol + 3][aRow] = av.w;
        *(float4*)&Bs[bRow][bCol] = bv;
        __syncthreads();

        #pragma unroll
        for (int k = 0; k < 8; ++k) {
            float a[8], b[8];
            #pragma unroll
            for (int i = 0; i < 8; ++i) a[i] = As[k][row0 + i];
            #pragma unroll
            for (int j = 0; j < 8; ++j) b[j] = Bs[k][col0 + j];
            #pragma unroll
            for (int i = 0; i < 8; ++i)
                #pragma unroll
                for (int j = 0; j < 8; ++j)
                    acc[i][j] = fmaf(a[i], b[j], acc[i][j]);
        }
        __syncthreads();
    }

    #pragma unroll
    for (int i = 0; i < 8; ++i) {
        float* cp = &C[(size_t)(m0 + row0 + i) * N + n0 + col0];
        *(float4*)(cp + 0) = make_float4(acc[i][0], acc[i][1], acc[i][2], acc[i][3]);
        *(float4*)(cp + 4) = make_float4(acc[i][4], acc[i][5], acc[i][6], acc[i][7]);
    }
}

// ---------------------------------------------------------------------------
// Attention per (window b, head h). One CTA each; grid (2048, 16).
// Reads qkv raw rows [b*49+l, 1536]: Q at col h*32, K at 512+h*32, V at 1024+h*32.
// Writes merged-head attention output [row, 512] at col h*32.
// ---------------------------------------------------------------------------
__global__ __launch_bounds__(256)
void attn_kernel(const float* __restrict__ qkv, const float* __restrict__ mask,
                 const float* __restrict__ bias_table, float* __restrict__ out) {
    const int b = blockIdx.x;
    const int h = blockIdx.y;

    __shared__ float Qs[L_TOK][33];
    __shared__ float Ks[L_TOK][33];
    __shared__ float Vs[L_TOK][33];
    __shared__ float S[L_TOK][52];

    const int tid = threadIdx.x;
    const float* base = qkv + (size_t)b * L_TOK * (3 * C_DIM) + h * HD_DIM;

    // Load Q, K, V tiles (49 x 32 each) as float4
    for (int i = tid; i < L_TOK * 8; i += 256) {
        int l  = i >> 3;
        int d4 = (i & 7) * 4;
        const float* p = base + (size_t)l * (3 * C_DIM) + d4;
        float4 q  = *(const float4*)(p);
        float4 kk = *(const float4*)(p + C_DIM);
        float4 v  = *(const float4*)(p + 2 * C_DIM);
        Qs[l][d4 + 0] = q.x;  Qs[l][d4 + 1] = q.y;  Qs[l][d4 + 2] = q.z;  Qs[l][d4 + 3] = q.w;
        Ks[l][d4 + 0] = kk.x; Ks[l][d4 + 1] = kk.y; Ks[l][d4 + 2] = kk.z; Ks[l][d4 + 3] = kk.w;
        Vs[l][d4 + 0] = v.x;  Vs[l][d4 + 1] = v.y;  Vs[l][d4 + 2] = v.z;  Vs[l][d4 + 3] = v.w;
    }
    __syncthreads();

    const int   win   = b & 63;
    const float scale = 0.1767766952966369f;  // 32^-0.5

    // Scores + bias + mask
    for (int e = tid; e < L_TOK * L_TOK; e += 256) {
        int l = e / L_TOK;
        int m = e - l * L_TOK;
        float s = 0.f;
        #pragma unroll
        for (int d = 0; d < HD_DIM; ++d) s = fmaf(Qs[l][d], Ks[m][d], s);
        int lh = l / 7, lw = l - lh * 7;
        int mh = m / 7, mw = m - mh * 7;
        int ri = (lh - mh + 6) * 13 + (lw - mw + 6);
        s = s * scale + bias_table[ri * H_HEADS + h]
                      + mask[((size_t)win * L_TOK + l) * L_TOK + m];
        S[l][m] = s;
    }
    __syncthreads();

    // Row softmax: one warp per row (rows strided by 8 warps)
    const int warp = tid >> 5;
    const int lane = tid & 31;
    for (int l = warp; l < L_TOK; l += 8) {
        float v0 = S[l][lane];
        float v1 = (lane < L_TOK - 32) ? S[l][lane + 32] : -1e30f;
        float mx = fmaxf(v0, v1);
        #pragma unroll
        for (int o = 16; o > 0; o >>= 1) mx = fmaxf(mx, __shfl_xor_sync(0xffffffffu, mx, o));
        float e0 = __expf(v0 - mx);
        float e1 = (lane < L_TOK - 32) ? __expf(v1 - mx) : 0.f;
        float sm = e0 + e1;
        #pragma unroll
        for (int o = 16; o > 0; o >>= 1) sm += __shfl_xor_sync(0xffffffffu, sm, o);
        float inv = 1.f / sm;
        S[l][lane] = e0 * inv;
        if (lane < L_TOK - 32) S[l][lane + 32] = e1 * inv;
    }
    __syncthreads();

    // O = P @ V, write merged heads
    float* ob = out + (size_t)b * L_TOK * C_DIM + h * HD_DIM;
    for (int e = tid; e < L_TOK * HD_DIM; e += 256) {
        int l = e >> 5;
        int d = e & 31;
        float s = 0.f;
        #pragma unroll
        for (int m = 0; m < L_TOK; ++m) s = fmaf(S[l][m], Vs[m][d], s);
        ob[(size_t)l * C_DIM + d] = s;
    }
}

// ---------------------------------------------------------------------------
// kernel_launch
// ---------------------------------------------------------------------------
extern "C" void kernel_launch(void* const* d_in, const int* in_sizes, int n_in,
                              void* d_out, int out_size) {
    const float* x     = (const float*)d_in[0];
    const float* mask  = (const float*)d_in[1];
    const float* bias  = (const float*)d_in[2];
    const float* wqkv  = (const float*)d_in[3];
    const float* wproj = (const float*)d_in[4];
    float*       out   = (float*)d_out;

    float* qkv = nullptr;
    float* att = nullptr;
    cudaGetSymbolAddress((void**)&qkv, g_qkv);
    cudaGetSymbolAddress((void**)&att, g_att);

    // 1) QKV projection: [100352, 512] x [512, 1536]
    sgemm128<<<dim3(1536 / 128, ROWS / 128), 256>>>(x, wqkv, qkv, ROWS, 3 * C_DIM, C_DIM);

    // 2) Windowed attention per (window, head)
    attn_kernel<<<dim3(B_TOT, H_HEADS), 256>>>(qkv, mask, bias, att);

    // 3) Output projection: [100352, 512] x [512, 512]
    sgemm128<<<dim3(C_DIM / 128, ROWS / 128), 256>>>(att, wproj, out, ROWS, C_DIM, C_DIM);
}

// round 2
// speedup vs baseline: 2.2272x; 2.2272x over previous
#include <cuda_runtime.h>
#include <math.h>

// ---------------------------------------------------------------------------
// Problem constants
//   x        [2048, 49, 512]   fp32
//   mask     [64, 49, 49]      fp32
//   bias_tab [169, 16]         fp32
//   w_qkv    [512, 1536]       fp32
//   w_proj   [512, 512]        fp32
//   out      [2048, 49, 512]   fp32
// ---------------------------------------------------------------------------

#define B_TOT   2048
#define L_TOK   49
#define C_DIM   512
#define H_HEADS 16
#define HD_DIM  32
#define ROWS    (B_TOT * L_TOK)        // 100352 = 784 * 128

// Scratch (device globals; allocation-free per harness rules)
static __device__ float g_qkv[(size_t)ROWS * 3 * C_DIM];  // 616 MB
static __device__ float g_att[(size_t)ROWS * C_DIM];      // 205 MB

// ---------------------------------------------------------------------------
// tf32 round-to-nearest
// ---------------------------------------------------------------------------
__device__ __forceinline__ float f2tf32(float x) {
    unsigned u;
    asm("cvt.rna.tf32.f32 %0, %1;" : "=r"(u) : "f"(x));
    return __uint_as_float(u);
}

// ---------------------------------------------------------------------------
// tf32 tensor-core GEMM: C[M,N] = A[M,K] * B[K,N]
// BM=128, BN=128, BK=16, 256 threads (8 warps), warp grid 2(m) x 4(n),
// warp tile 64x32 via mma.sync.m16n8k8 (4 m-tiles x 4 n-tiles).
// Requires M%128==0, N%128==0, K%16==0.
//
// Smem: As [128][20]  (row-major, stride 20 -> conflict-free frag loads)
//       Bs [16][136]  (row-major, stride 136 -> conflict-free frag loads)
// ---------------------------------------------------------------------------
#define ASTR 20
#define BSTR 136

__global__ __launch_bounds__(256, 2)
void gemm_tf32(const float* __restrict__ A, const float* __restrict__ B,
               float* __restrict__ C, int M, int N, int K) {
    __shared__ float As[128 * ASTR];
    __shared__ float Bs[16 * BSTR];

    const int tid  = threadIdx.x;
    const int lane = tid & 31;
    const int warp = tid >> 5;
    const int wm   = warp >> 2;          // 0..1
    const int wn   = warp & 3;           // 0..3
    const int g    = lane >> 2;          // group 0..7
    const int t    = lane & 3;           // thread-in-group 0..3

    const int m0 = blockIdx.y * 128;
    const int n0 = blockIdx.x * 128;

    // Global load mapping
    const int a_m = tid >> 2;            // 0..63 (also +64)
    const int a_k = (tid & 3) * 4;
    const int b_k = tid >> 5;            // 0..7 (also +8)
    const int b_n = (tid & 31) * 4;

    const float* Ag = A + (size_t)(m0 + a_m) * K + a_k;
    const float* Bg = B + (size_t)b_k * N + n0 + b_n;

    float acc[16][4];
    #pragma unroll
    for (int i = 0; i < 16; ++i)
        #pragma unroll
        for (int j = 0; j < 4; ++j) acc[i][j] = 0.f;

    // Prefetch tile 0
    float4 pa0 = *(const float4*)(Ag);
    float4 pa1 = *(const float4*)(Ag + (size_t)64 * K);
    float4 pb0 = *(const float4*)(Bg);
    float4 pb1 = *(const float4*)(Bg + (size_t)8 * N);

    const int nK = K >> 4;
    for (int kt = 0; kt < nK; ++kt) {
        // Store prefetched tile to smem (with tf32 rounding)
        {
            float* ap = &As[a_m * ASTR + a_k];
            ap[0] = f2tf32(pa0.x); ap[1] = f2tf32(pa0.y);
            ap[2] = f2tf32(pa0.z); ap[3] = f2tf32(pa0.w);
            float* ap2 = ap + 64 * ASTR;
            ap2[0] = f2tf32(pa1.x); ap2[1] = f2tf32(pa1.y);
            ap2[2] = f2tf32(pa1.z); ap2[3] = f2tf32(pa1.w);
            float* bp = &Bs[b_k * BSTR + b_n];
            bp[0] = f2tf32(pb0.x); bp[1] = f2tf32(pb0.y);
            bp[2] = f2tf32(pb0.z); bp[3] = f2tf32(pb0.w);
            float* bp2 = bp + 8 * BSTR;
            bp2[0] = f2tf32(pb1.x); bp2[1] = f2tf32(pb1.y);
            bp2[2] = f2tf32(pb1.z); bp2[3] = f2tf32(pb1.w);
        }
        __syncthreads();

        // Prefetch next tile
        if (kt + 1 < nK) {
            const float* An = Ag + (kt + 1) * 16;
            const float* Bn = Bg + (size_t)(kt + 1) * 16 * N;
            pa0 = *(const float4*)(An);
            pa1 = *(const float4*)(An + (size_t)64 * K);
            pb0 = *(const float4*)(Bn);
            pb1 = *(const float4*)(Bn + (size_t)8 * N);
        }

        // Compute: kk in {0, 8}
        #pragma unroll
        for (int kk = 0; kk < 16; kk += 8) {
            // A fragments: 4 m-tiles
            float af[4][4];
            #pragma unroll
            for (int mt = 0; mt < 4; ++mt) {
                const float* ap = &As[(wm * 64 + mt * 16 + g) * ASTR + kk + t];
                af[mt][0] = ap[0];
                af[mt][1] = ap[8 * ASTR];
                af[mt][2] = ap[4];
                af[mt][3] = ap[8 * ASTR + 4];
            }
            // B fragments: 4 n-tiles
            float bf[4][2];
            #pragma unroll
            for (int nt = 0; nt < 4; ++nt) {
                const float* bp = &Bs[(kk + t) * BSTR + wn * 32 + nt * 8 + g];
                bf[nt][0] = bp[0];
                bf[nt][1] = bp[4 * BSTR];
            }
            #pragma unroll
            for (int mt = 0; mt < 4; ++mt)
                #pragma unroll
                for (int nt = 0; nt < 4; ++nt) {
                    float* c = acc[mt * 4 + nt];
                    asm volatile(
                        "mma.sync.aligned.m16n8k8.row.col.f32.tf32.tf32.f32 "
                        "{%0,%1,%2,%3}, {%4,%5,%6,%7}, {%8,%9}, {%0,%1,%2,%3};\n"
                        : "+f"(c[0]), "+f"(c[1]), "+f"(c[2]), "+f"(c[3])
                        : "r"(__float_as_uint(af[mt][0])), "r"(__float_as_uint(af[mt][1])),
                          "r"(__float_as_uint(af[mt][2])), "r"(__float_as_uint(af[mt][3])),
                          "r"(__float_as_uint(bf[nt][0])), "r"(__float_as_uint(bf[nt][1])));
                }
        }
        __syncthreads();
    }

    // Epilogue: write 16 fragments, float2 per row-half
    #pragma unroll
    for (int mt = 0; mt < 4; ++mt) {
        #pragma unroll
        for (int nt = 0; nt < 4; ++nt) {
            const float* c = acc[mt * 4 + nt];
            int row = m0 + wm * 64 + mt * 16 + g;
            int col = n0 + wn * 32 + nt * 8 + t * 2;
            *(float2*)&C[(size_t)row * N + col]       = make_float2(c[0], c[1]);
            *(float2*)&C[(size_t)(row + 8) * N + col] = make_float2(c[2], c[3]);
        }
    }
}

// ---------------------------------------------------------------------------
// Attention per (window b, head h). One CTA each; grid (2048, 16).
// ---------------------------------------------------------------------------
__global__ __launch_bounds__(256)
void attn_kernel(const float* __restrict__ qkv, const float* __restrict__ mask,
                 const float* __restrict__ bias_table, float* __restrict__ out) {
    const int b = blockIdx.x;
    const int h = blockIdx.y;

    __shared__ float Qs[L_TOK][33];
    __shared__ float Ks[L_TOK][33];
    __shared__ float Vs[L_TOK][33];
    __shared__ float S[L_TOK][52];

    const int tid = threadIdx.x;
    const float* base = qkv + (size_t)b * L_TOK * (3 * C_DIM) + h * HD_DIM;

    for (int i = tid; i < L_TOK * 8; i += 256) {
        int l  = i >> 3;
        int d4 = (i & 7) * 4;
        const float* p = base + (size_t)l * (3 * C_DIM) + d4;
        float4 q  = *(const float4*)(p);
        float4 kk = *(const float4*)(p + C_DIM);
        float4 v  = *(const float4*)(p + 2 * C_DIM);
        Qs[l][d4 + 0] = q.x;  Qs[l][d4 + 1] = q.y;  Qs[l][d4 + 2] = q.z;  Qs[l][d4 + 3] = q.w;
        Ks[l][d4 + 0] = kk.x; Ks[l][d4 + 1] = kk.y; Ks[l][d4 + 2] = kk.z; Ks[l][d4 + 3] = kk.w;
        Vs[l][d4 + 0] = v.x;  Vs[l][d4 + 1] = v.y;  Vs[l][d4 + 2] = v.z;  Vs[l][d4 + 3] = v.w;
    }
    __syncthreads();

    const int   win   = b & 63;
    const float scale = 0.1767766952966369f;  // 32^-0.5

    for (int e = tid; e < L_TOK * L_TOK; e += 256) {
        int l = e / L_TOK;
        int m = e - l * L_TOK;
        float s = 0.f;
        #pragma unroll
        for (int d = 0; d < HD_DIM; ++d) s = fmaf(Qs[l][d], Ks[m][d], s);
        int lh = l / 7, lw = l - lh * 7;
        int mh = m / 7, mw = m - mh * 7;
        int ri = (lh - mh + 6) * 13 + (lw - mw + 6);
        s = s * scale + bias_table[ri * H_HEADS + h]
                      + mask[((size_t)win * L_TOK + l) * L_TOK + m];
        S[l][m] = s;
    }
    __syncthreads();

    const int warp = tid >> 5;
    const int lane = tid & 31;
    for (int l = warp; l < L_TOK; l += 8) {
        float v0 = S[l][lane];
        float v1 = (lane < L_TOK - 32) ? S[l][lane + 32] : -1e30f;
        float mx = fmaxf(v0, v1);
        #pragma unroll
        for (int o = 16; o > 0; o >>= 1) mx = fmaxf(mx, __shfl_xor_sync(0xffffffffu, mx, o));
        float e0 = __expf(v0 - mx);
        float e1 = (lane < L_TOK - 32) ? __expf(v1 - mx) : 0.f;
        float sm = e0 + e1;
        #pragma unroll
        for (int o = 16; o > 0; o >>= 1) sm += __shfl_xor_sync(0xffffffffu, sm, o);
        float inv = 1.f / sm;
        S[l][lane] = e0 * inv;
        if (lane < L_TOK - 32) S[l][lane + 32] = e1 * inv;
    }
    __syncthreads();

    float* ob = out + (size_t)b * L_TOK * C_DIM + h * HD_DIM;
    for (int e = tid; e < L_TOK * HD_DIM; e += 256) {
        int l = e >> 5;
        int d = e & 31;
        float s = 0.f;
        #pragma unroll
        for (int m = 0; m < L_TOK; ++m) s = fmaf(S[l][m], Vs[m][d], s);
        ob[(size_t)l * C_DIM + d] = s;
    }
}

// ---------------------------------------------------------------------------
// kernel_launch
// ---------------------------------------------------------------------------
extern "C" void kernel_launch(void* const* d_in, const int* in_sizes, int n_in,
                              void* d_out, int out_size) {
    const float* x     = (const float*)d_in[0];
    const float* mask  = (const float*)d_in[1];
    const float* bias  = (const float*)d_in[2];
    const float* wqkv  = (const float*)d_in[3];
    const float* wproj = (const float*)d_in[4];
    float*       out   = (float*)d_out;

    float* qkv = nullptr;
    float* att = nullptr;
    cudaGetSymbolAddress((void**)&qkv, g_qkv);
    cudaGetSymbolAddress((void**)&att, g_att);

    // 1) QKV projection: [100352, 512] x [512, 1536]  (tf32 tensor cores)
    gemm_tf32<<<dim3(1536 / 128, ROWS / 128), 256>>>(x, wqkv, qkv, ROWS, 3 * C_DIM, C_DIM);

    // 2) Windowed attention per (window, head)
    attn_kernel<<<dim3(B_TOT, H_HEADS), 256>>>(qkv, mask, bias, att);

    // 3) Output projection: [100352, 512] x [512, 512]  (tf32 tensor cores)
    gemm_tf32<<<dim3(C_DIM / 128, ROWS / 128), 256>>>(att, wproj, out, ROWS, C_DIM, C_DIM);
}